// round 6
// baseline (speedup 1.0000x reference)
#include <cuda_runtime.h>
#include <cstdint>

#define N_NODES 100000
#define D_IN    512
#define D_HID   256
#define D_OUT   32

// Scratch (device globals: no runtime allocation allowed)
__device__ float g_x[(size_t)N_NODES * D_OUT];   // 12.8 MB
__device__ float g_w1t[D_HID * D_IN];            // W1^T, tf32-rounded

// ---------------------------------------------------------------------------
__device__ __forceinline__ float tf32_rna(float x) {
    uint32_t u;
    asm("cvt.rna.tf32.f32 %0, %1;" : "=r"(u) : "f"(x));
    return __uint_as_float(u);
}

__device__ __forceinline__ void mma_tf32(
    float& d0, float& d1, float& d2, float& d3,
    float a0, float a1, float a2, float a3,
    float b0, float b1)
{
    asm volatile(
        "mma.sync.aligned.m16n8k8.row.col.f32.tf32.tf32.f32 "
        "{%0,%1,%2,%3},{%4,%5,%6,%7},{%8,%9},{%0,%1,%2,%3};"
        : "+f"(d0), "+f"(d1), "+f"(d2), "+f"(d3)
        : "r"(__float_as_uint(a0)), "r"(__float_as_uint(a1)),
          "r"(__float_as_uint(a2)), "r"(__float_as_uint(a3)),
          "r"(__float_as_uint(b0)), "r"(__float_as_uint(b1)));
}

__device__ __forceinline__ void red_v2(float* p, float v0, float v1) {
    asm volatile("red.global.add.v2.f32 [%0], {%1, %2};"
                 :: "l"(p), "f"(v0), "f"(v1) : "memory");
}

// ---------------------------------------------------------------------------
// Prep: W1[k][n] -> g_w1t[n][k], tf32-rounded. grid(16,8), block(32,8)
// ---------------------------------------------------------------------------
__global__ void prep_w1_kernel(const float* __restrict__ W1) {
    __shared__ float tile[32][33];
    const int tx = threadIdx.x;
    const int ty = threadIdx.y;
    const int kb = blockIdx.x * 32;
    const int nb = blockIdx.y * 32;
#pragma unroll
    for (int i = 0; i < 4; i++) {
        int k = ty + i * 8;
        tile[k][tx] = W1[(size_t)(kb + k) * D_HID + nb + tx];
    }
    __syncthreads();
#pragma unroll
    for (int i = 0; i < 4; i++) {
        int n = ty + i * 8;
        g_w1t[(size_t)(nb + n) * D_IN + kb + tx] = tf32_rna(tile[tx][n]);
    }
}

// ---------------------------------------------------------------------------
// Init: g_x[n][c] = b2[c] (epilogue accumulates into it); out = 0
// ---------------------------------------------------------------------------
__global__ void init_kernel(float4* out, int n4_out, const float* __restrict__ b2)
{
    int i = blockIdx.x * blockDim.x + threadIdx.x;
    if (i < n4_out) {
        out[i] = make_float4(0.f, 0.f, 0.f, 0.f);
    } else {
        int j = i - n4_out;
        if (j < N_NODES * (D_OUT / 4)) {
            int c = (j * 4) & (D_OUT - 1);
            float4 v;
            v.x = __ldg(b2 + c);     v.y = __ldg(b2 + c + 1);
            v.z = __ldg(b2 + c + 2); v.w = __ldg(b2 + c + 3);
            ((float4*)g_x)[j] = v;
        }
    }
}

// ---------------------------------------------------------------------------
// Fused GEMM: X += relu(F @ W1 + b1)[:, n0:n0+64] @ W2[n0:n0+64, :]
// CTA 128x64x32, 256 threads, 8 warps (4M x 2N), warp tile 32x32,
// 2 CTAs/SM (barrier decoupling). k-permuted smem: c -> (c&3)*8 + (c>>2),
// row stride 36. Epilogue on tensor cores, red into g_x.
// SMEM (floats): A0 @0 (4608)  A1 @4608  B0 @9216 (2304)  B1 @11520
//                w2p @13824 (2304)   -> 16128 fl = 64512 B
// ---------------------------------------------------------------------------
#define G1_BK    32
#define G1_KIT   (D_IN / G1_BK)      // 16
#define G1_LD    36
#define A_BUF    4608                // 128*36
#define B_BUF    2304                // 64*36
#define OFF_B    (2 * A_BUF)         // 9216
#define OFF_W2P  (OFF_B + 2 * B_BUF) // 13824
#define W2P_KB   1152                // 32*36
#define G1_SMEM  ((OFF_W2P + 2 * W2P_KB) * 4)   // 64512 bytes

__global__ __launch_bounds__(256, 2) void gemm_fused_kernel(
    const float* __restrict__ F,
    const float* __restrict__ b1,
    const float* __restrict__ W2)
{
    extern __shared__ float sm[];
    float* w2p = sm + OFF_W2P;

    const int t    = threadIdx.x;
    const int lane = t & 31;
    const int wid  = t >> 5;           // 0..7
    const int wm   = wid & 3;          // warp M (0..3)
    const int wn   = wid >> 2;         // warp N (0..1)
    const int g    = lane >> 2;        // 0..7
    const int tig  = lane & 3;         // 0..3

    const int n0 = blockIdx.x * 64;    // N fastest -> F L2 reuse
    const int m0 = blockIdx.y * 128;

    // ---- pre-permute W2 slice [n0:n0+64, 0:32] into w2p (tf32-rounded) ----
#pragma unroll
    for (int i = 0; i < 8; i++) {
        int idx = t + i * 256;                  // 0..2047
        int c   = idx >> 5;                     // h-col 0..63
        int np  = idx & 31;                     // out col
        float v = tf32_rna(W2[(size_t)(n0 + c) * D_OUT + np]);
        int cc  = c & 31;
        int pos = (cc & 3) * 8 + (cc >> 2);
        w2p[(c >> 5) * W2P_KB + np * G1_LD + pos] = v;
    }

    // ---- staging: A row = t>>1, kq = (t&1)*16 (4 float4);
    //               B row = t>>2, kqb = (t&3)*8 (2 float4) ----
    const int arow_l = t >> 1;
    const int kqa    = (t & 1) * 16;
    const int brow_l = t >> 2;
    const int kqb    = (t & 3) * 8;

    int arow = m0 + arow_l;
    if (arow >= N_NODES) arow = N_NODES - 1;   // clamp; stores guarded
    const float* Ag = F + (size_t)arow * D_IN + kqa;
    const float* Bg = g_w1t + (size_t)(n0 + brow_l) * D_IN + kqb;

    const int pa = arow_l * G1_LD + 4 * (t & 1);   // + q + 8e
    const int pb = brow_l * G1_LD + 2 * (t & 3);   // + q + 8e

    float4 ra[4], rb[2];
#pragma unroll
    for (int q = 0; q < 4; q++) ra[q] = *(const float4*)(Ag + q * 4);
#pragma unroll
    for (int q = 0; q < 2; q++) rb[q] = *(const float4*)(Bg + q * 4);

    {
        float* As = sm;
        float* Bs = sm + OFF_B;
#pragma unroll
        for (int q = 0; q < 4; q++) {
            As[pa + q + 0 ] = ra[q].x;
            As[pa + q + 8 ] = ra[q].y;
            As[pa + q + 16] = ra[q].z;
            As[pa + q + 24] = ra[q].w;
        }
#pragma unroll
        for (int q = 0; q < 2; q++) {
            Bs[pb + q + 0 ] = rb[q].x;
            Bs[pb + q + 8 ] = rb[q].y;
            Bs[pb + q + 16] = rb[q].z;
            Bs[pb + q + 24] = rb[q].w;
        }
    }
    __syncthreads();

    float acc[2][4][4];
#pragma unroll
    for (int i = 0; i < 2; i++)
#pragma unroll
        for (int j = 0; j < 4; j++)
#pragma unroll
            for (int c = 0; c < 4; c++) acc[i][j][c] = 0.f;

    const int am = wm * 32;
    const int bn = wn * 32;

    for (int kb = 0; kb < G1_KIT; kb++) {
        if (kb + 1 < G1_KIT) {
            const float* pA = Ag + (kb + 1) * G1_BK;
            const float* pB = Bg + (kb + 1) * G1_BK;
#pragma unroll
            for (int q = 0; q < 4; q++) ra[q] = *(const float4*)(pA + q * 4);
#pragma unroll
            for (int q = 0; q < 2; q++) rb[q] = *(const float4*)(pB + q * 4);
        }

        const float* As = sm + (kb & 1) * A_BUF;
        const float* Bs = sm + OFF_B + (kb & 1) * B_BUF;

#pragma unroll
        for (int j = 0; j < 2; j++) {
            float4 afl[2], afh[2], bf[4];
#pragma unroll
            for (int mt = 0; mt < 2; mt++) {
                int r = am + mt * 16 + g;
                afl[mt] = *(const float4*)(As + r * G1_LD + tig * 8 + j * 4);
                afh[mt] = *(const float4*)(As + (r + 8) * G1_LD + tig * 8 + j * 4);
            }
#pragma unroll
            for (int nt = 0; nt < 4; nt++) {
                int n = bn + nt * 8 + g;
                bf[nt] = *(const float4*)(Bs + n * G1_LD + tig * 8 + j * 4);
            }
#pragma unroll
            for (int mt = 0; mt < 2; mt++) {
#pragma unroll
                for (int nt = 0; nt < 4; nt++) {
                    mma_tf32(acc[mt][nt][0], acc[mt][nt][1],
                             acc[mt][nt][2], acc[mt][nt][3],
                             afl[mt].x, afh[mt].x, afl[mt].y, afh[mt].y,
                             bf[nt].x,  bf[nt].y);
                    mma_tf32(acc[mt][nt][0], acc[mt][nt][1],
                             acc[mt][nt][2], acc[mt][nt][3],
                             afl[mt].z, afh[mt].z, afl[mt].w, afh[mt].w,
                             bf[nt].z,  bf[nt].w);
                }
            }
        }

        if (kb + 1 < G1_KIT) {
            float* Aw = sm + ((kb + 1) & 1) * A_BUF;
            float* Bw = sm + OFF_B + ((kb + 1) & 1) * B_BUF;
#pragma unroll
            for (int q = 0; q < 4; q++) {
                Aw[pa + q + 0 ] = ra[q].x;
                Aw[pa + q + 8 ] = ra[q].y;
                Aw[pa + q + 16] = ra[q].z;
                Aw[pa + q + 24] = ra[q].w;
            }
#pragma unroll
            for (int q = 0; q < 2; q++) {
                Bw[pb + q + 0 ] = rb[q].x;
                Bw[pb + q + 8 ] = rb[q].y;
                Bw[pb + q + 16] = rb[q].z;
                Bw[pb + q + 24] = rb[q].w;
            }
            __syncthreads();
        }
    }

    // ---- epilogue 1: bias + relu -> A staging buffers (k-permuted, tf32) ----
    __syncthreads();
    {
        float* hb = sm + wn * A_BUF;    // h cols [wn*32, +32) of this CTA tile
#pragma unroll
        for (int mt = 0; mt < 2; mt++) {
            const int lr = am + mt * 16 + g;
#pragma unroll
            for (int nt = 0; nt < 4; nt++) {
                const int cc  = nt * 8 + 2 * tig;          // 0..31 (even)
                const int pos = (cc & 3) * 8 + (cc >> 2);
                const float bx = __ldg(b1 + n0 + wn * 32 + cc);
                const float by = __ldg(b1 + n0 + wn * 32 + cc + 1);
                hb[lr * G1_LD + pos]           = tf32_rna(fmaxf(acc[mt][nt][0] + bx, 0.f));
                hb[lr * G1_LD + pos + 8]       = tf32_rna(fmaxf(acc[mt][nt][1] + by, 0.f));
                hb[(lr + 8) * G1_LD + pos]     = tf32_rna(fmaxf(acc[mt][nt][2] + bx, 0.f));
                hb[(lr + 8) * G1_LD + pos + 8] = tf32_rna(fmaxf(acc[mt][nt][3] + by, 0.f));
            }
        }
    }
    __syncthreads();

    // ---- epilogue 2: X partial = h(128x64) @ W2slice(64x32) via mma ----
    // 8 warps: warp wid -> m rows [16*wid, +16), full 32 out cols.
    {
        float xc[4][4];
#pragma unroll
        for (int nt = 0; nt < 4; nt++)
#pragma unroll
            for (int c = 0; c < 4; c++) xc[nt][c] = 0.f;

#pragma unroll
        for (int kb2 = 0; kb2 < 2; kb2++) {
            const float* Ah = sm + kb2 * A_BUF;
            const float* Wp = w2p + kb2 * W2P_KB;
#pragma unroll
            for (int j = 0; j < 2; j++) {
                float4 al = *(const float4*)(Ah + (wid * 16 + g) * G1_LD + tig * 8 + j * 4);
                float4 ah = *(const float4*)(Ah + (wid * 16 + g + 8) * G1_LD + tig * 8 + j * 4);
#pragma unroll
                for (int nt = 0; nt < 4; nt++) {
                    float4 bw = *(const float4*)(Wp + (nt * 8 + g) * G1_LD + tig * 8 + j * 4);
                    mma_tf32(xc[nt][0], xc[nt][1], xc[nt][2], xc[nt][3],
                             al.x, ah.x, al.y, ah.y, bw.x, bw.y);
                    mma_tf32(xc[nt][0], xc[nt][1], xc[nt][2], xc[nt][3],
                             al.z, ah.z, al.w, ah.w, bw.z, bw.w);
                }
            }
        }

        const int mrow = m0 + wid * 16 + g;
#pragma unroll
        for (int nt = 0; nt < 4; nt++) {
            const int np = nt * 8 + 2 * tig;
            if (mrow < N_NODES)
                red_v2(g_x + (size_t)mrow * D_OUT + np, xc[nt][0], xc[nt][1]);
            if (mrow + 8 < N_NODES)
                red_v2(g_x + (size_t)(mrow + 8) * D_OUT + np, xc[nt][2], xc[nt][3]);
        }
    }
}

// ---------------------------------------------------------------------------
// Scatter: out[A_row[e], :] += A_data[e] * X[A_col[e], :]  (v2 reductions)
// ---------------------------------------------------------------------------
__global__ __launch_bounds__(256) void scatter_kernel(
    const float* __restrict__ A_data,
    const int*   __restrict__ A_row,
    const int*   __restrict__ A_col,
    float*       __restrict__ out,
    int n_edges)
{
    int idx = blockIdx.x * blockDim.x + threadIdx.x;
    int e = idx >> 3;
    int q = idx & 7;
    if (e >= n_edges) return;

    float a = __ldg(A_data + e);
    int   r = __ldg(A_row + e);
    int   c = __ldg(A_col + e);

    float4 xv = *(const float4*)(g_x + (size_t)c * D_OUT + q * 4);
    float* o  = out + (size_t)r * D_OUT + q * 4;
    red_v2(o + 0, a * xv.x, a * xv.y);
    red_v2(o + 2, a * xv.z, a * xv.w);
}

// ---------------------------------------------------------------------------
extern "C" void kernel_launch(void* const* d_in, const int* in_sizes, int n_in,
                              void* d_out, int out_size)
{
    const float* F      = (const float*)d_in[0];
    const float* A_data = (const float*)d_in[1];
    const float* W1     = (const float*)d_in[2];
    const float* b1     = (const float*)d_in[3];
    const float* W2     = (const float*)d_in[4];
    const float* b2     = (const float*)d_in[5];
    const int*   A_row  = (const int*)d_in[6];
    const int*   A_col  = (const int*)d_in[7];
    float* out = (float*)d_out;

    const int n_edges = in_sizes[1];

    cudaFuncSetAttribute(gemm_fused_kernel,
                         cudaFuncAttributeMaxDynamicSharedMemorySize, G1_SMEM);

    // W1 transpose + tf32 rounding
    prep_w1_kernel<<<dim3(D_IN / 32, D_HID / 32), dim3(32, 8)>>>(W1);

    // out = 0, g_x = b2
    const int n4_out = out_size / 4;
    const int n4_x   = N_NODES * D_OUT / 4;
    init_kernel<<<(n4_out + n4_x + 255) / 256, 256>>>((float4*)out, n4_out, b2);

    // Fused GEMM (N fastest for F L2 reuse; 2 CTAs/SM)
    dim3 g1(D_HID / 64, (N_NODES + 127) / 128);
    gemm_fused_kernel<<<g1, 256, G1_SMEM>>>(F, b1, W2);

    // Scatter
    long long tot = (long long)n_edges * 8;
    int blocks = (int)((tot + 255) / 256);
    scatter_kernel<<<blocks, 256>>>(A_data, A_row, A_col, out, n_edges);
}